// round 16
// baseline (speedup 1.0000x reference)
#include <cuda_runtime.h>

static constexpr int  B      = 256;
static constexpr int  H      = 512;
static constexpr long N_ELEM = 256L * 3 * 64 * 64;   // 3,145,728
static constexpr long N4     = N_ELEM / 4;           // 786,432 float4
static constexpr int  GRID   = 512;                  // measured optimum
static constexpr int  TPB    = 256;
static constexpr int  ITERS  = (int)(N4 / ((long)GRID * TPB));  // == 6, exact
static constexpr int  NWARP  = TPB / 32;             // 8

// Global accumulators: zero at module load; last block resets them every
// launch so each graph replay starts from zero.
__device__ float        g_acc_mse;
__device__ float        g_acc_pt;
__device__ unsigned int g_count;

__device__ __forceinline__ float warp_reduce_f(float v) {
    #pragma unroll
    for (int off = 16; off > 0; off >>= 1)
        v += __shfl_xor_sync(0xFFFFFFFFu, v, off);
    return v;
}

__global__ void __launch_bounds__(TPB)
fused_loss_kernel(const float4* __restrict__ y4,
                  const float4* __restrict__ x4,
                  const float2* __restrict__ z2,
                  float* __restrict__ out)
{
    const int tid  = threadIdx.x;
    const int lane = tid & 31;
    const int wid  = tid >> 5;
    const bool has_z = (blockIdx.x < B);   // uniform per block

    __shared__ float s_mse[NWARP];
    __shared__ float s_s2[NWARP];
    __shared__ float s_s4[NWARP];

    const long base   = (long)blockIdx.x * TPB + tid;
    const long stride = (long)GRID * TPB;

    // z row: blocks 0..255, 2 floats/thread (256*2 = 512 = H)
    float2 zv = make_float2(0.f, 0.f);
    if (has_z) zv = z2[(long)blockIdx.x * (H / 2) + tid];

    // ---- MSE: depth-2 software pipeline over 6 exact iterations ----
    float4 yc = y4[base];
    float4 xc = x4[base];
    float acc = 0.0f;

    #pragma unroll
    for (int k = 0; k < ITERS; k++) {
        float4 yn, xn;
        if (k + 1 < ITERS) {
            yn = y4[base + (k + 1) * stride];
            xn = x4[base + (k + 1) * stride];
        }
        float d0 = yc.x - xc.x;
        float d1 = yc.y - xc.y;
        float d2 = yc.z - xc.z;
        float d3 = yc.w - xc.w;
        acc += d0 * d0 + d1 * d1 + d2 * d2 + d3 * d3;
        if (k + 1 < ITERS) { yc = yn; xc = xn; }
    }

    acc = warp_reduce_f(acc);
    if (lane == 0) s_mse[wid] = acc;

    // ---- z math: per-row sum(z^2), sum(z^4); only z-owning blocks reduce ----
    if (has_z) {
        float q0 = zv.x * zv.x, q1 = zv.y * zv.y;
        float s2 = warp_reduce_f(q0 + q1);
        float s4 = warp_reduce_f(q0 * q0 + q1 * q1);
        if (lane == 0) { s_s2[wid] = s2; s_s4[wid] = s4; }
    }
    __syncthreads();

    // ---- thread 0: combine, no-return REDs, release-counter, finalize ----
    if (tid == 0) {
        float m = 0.f;
        #pragma unroll
        for (int w = 0; w < NWARP; w++) m += s_mse[w];
        atomicAdd(&g_acc_mse, m);                        // no-return -> REDG

        if (has_z) {
            float t2 = 0.f, t4 = 0.f;
            #pragma unroll
            for (int w = 0; w < NWARP; w++) { t2 += s_s2[w]; t4 += s_s4[w]; }
            double d2 = (double)t2;
            atomicAdd(&g_acc_pt, (float)(1.0 - (double)t4 / (d2 * d2)));
        }

        // release-atomic orders the REDs above; no standalone gpu fence
        unsigned prev;
        asm volatile("atom.add.release.gpu.global.u32 %0, [%1], %2;"
                     : "=r"(prev) : "l"(&g_count), "r"(1u) : "memory");

        if (prev == (unsigned)(GRID - 1)) {
            // last arrival: same-address atomic RMWs serialize behind all
            // prior REDs at the LTS -> complete sums observed
            float sum_sq = atomicAdd(&g_acc_mse, 0.0f);
            float sum_pt = atomicAdd(&g_acc_pt, 0.0f);

            double mse = (double)sum_sq / (double)N_ELEM;
            double pt  = (double)sum_pt / ((double)B * (double)H * (double)H);
            out[0] = (float)(mse + 0.1 * pt);

            // reset for next graph replay
            g_acc_mse = 0.0f;
            g_acc_pt  = 0.0f;
            asm volatile("st.release.gpu.global.u32 [%0], %1;"
                         :: "l"(&g_count), "r"(0u) : "memory");
        }
    }
}

extern "C" void kernel_launch(void* const* d_in, const int* in_sizes, int n_in,
                              void* d_out, int out_size)
{
    const float4* y4 = (const float4*)d_in[0];   // yhat_xhat
    const float4* x4 = (const float4*)d_in[1];   // xhat
    const float2* z2 = (const float2*)d_in[2];   // z_xhat
    float* out = (float*)d_out;

    fused_loss_kernel<<<GRID, TPB>>>(y4, x4, z2, out);
}

// round 17
// speedup vs baseline: 1.2657x; 1.2657x over previous
#include <cuda_runtime.h>

static constexpr int  B      = 256;
static constexpr int  H      = 512;
static constexpr long N_ELEM = 256L * 3 * 64 * 64;   // 3,145,728
static constexpr long N4     = N_ELEM / 4;           // 786,432 float4
static constexpr int  GRID   = 512;                  // measured optimum
static constexpr int  TPB    = 256;
static constexpr int  ITERS  = (int)(N4 / ((long)GRID * TPB));  // == 6, exact
static constexpr int  NWARP  = TPB / 32;             // 8

// Global accumulators: zero at module load; last block resets them every
// launch so each graph replay starts from zero.
__device__ float        g_acc_mse;
__device__ float        g_acc_pt;
__device__ unsigned int g_count;

__device__ __forceinline__ float warp_reduce_f(float v) {
    #pragma unroll
    for (int off = 16; off > 0; off >>= 1)
        v += __shfl_xor_sync(0xFFFFFFFFu, v, off);
    return v;
}

__global__ void __launch_bounds__(TPB)
fused_loss_kernel(const float4* __restrict__ y4,
                  const float4* __restrict__ x4,
                  const float2* __restrict__ z2,
                  float* __restrict__ out)
{
    const int tid  = threadIdx.x;
    const int lane = tid & 31;
    const int wid  = tid >> 5;
    const bool has_z = (blockIdx.x < B);

    __shared__ float s_mse[NWARP];
    __shared__ float s_s2[NWARP];
    __shared__ float s_s4[NWARP];

    const long base   = (long)blockIdx.x * TPB + tid;
    const long stride = (long)GRID * TPB;

    // z row: blocks 0..255, 2 floats/thread (256*2 = 512 = H)
    float2 zv = make_float2(0.f, 0.f);
    if (has_z) zv = z2[(long)blockIdx.x * (H / 2) + tid];

    // ---- MSE: depth-2 software pipeline over 6 exact iterations ----
    float4 yc = y4[base];
    float4 xc = x4[base];
    float acc = 0.0f;

    #pragma unroll
    for (int k = 0; k < ITERS; k++) {
        float4 yn, xn;
        if (k + 1 < ITERS) {
            yn = y4[base + (k + 1) * stride];
            xn = x4[base + (k + 1) * stride];
        }
        float d0 = yc.x - xc.x;
        float d1 = yc.y - xc.y;
        float d2 = yc.z - xc.z;
        float d3 = yc.w - xc.w;
        acc += d0 * d0 + d1 * d1 + d2 * d2 + d3 * d3;
        if (k + 1 < ITERS) { yc = yn; xc = xn; }
    }

    // ---- z math: per-row sum(z^2), sum(z^4); cos-term = 1 - s4/s2^2 ----
    float q0 = zv.x * zv.x, q1 = zv.y * zv.y;
    float s2 = q0 + q1;
    float s4 = q0 * q0 + q1 * q1;

    acc = warp_reduce_f(acc);
    s2  = warp_reduce_f(s2);
    s4  = warp_reduce_f(s4);
    if (lane == 0) { s_mse[wid] = acc; s_s2[wid] = s2; s_s4[wid] = s4; }
    __syncthreads();

    // ---- thread 0: combine, no-return REDs, release-counter, finalize ----
    if (tid == 0) {
        float m = 0.f, t2 = 0.f, t4 = 0.f;
        #pragma unroll
        for (int w = 0; w < NWARP; w++) { m += s_mse[w]; t2 += s_s2[w]; t4 += s_s4[w]; }

        atomicAdd(&g_acc_mse, m);                        // no-return -> REDG
        if (has_z) {
            double d2 = (double)t2;
            atomicAdd(&g_acc_pt, (float)(1.0 - (double)t4 / (d2 * d2)));
        }

        // release-atomic orders the REDs above; no standalone gpu fence
        unsigned prev;
        asm volatile("atom.add.release.gpu.global.u32 %0, [%1], %2;"
                     : "=r"(prev) : "l"(&g_count), "r"(1u) : "memory");

        if (prev == (unsigned)(GRID - 1)) {
            // last arrival: same-address atomic RMWs serialize behind all
            // prior REDs at the LTS -> complete sums observed
            float sum_sq = atomicAdd(&g_acc_mse, 0.0f);
            float sum_pt = atomicAdd(&g_acc_pt, 0.0f);

            double mse = (double)sum_sq / (double)N_ELEM;
            double pt  = (double)sum_pt / ((double)B * (double)H * (double)H);
            out[0] = (float)(mse + 0.1 * pt);

            // reset for next graph replay
            g_acc_mse = 0.0f;
            g_acc_pt  = 0.0f;
            asm volatile("st.release.gpu.global.u32 [%0], %1;"
                         :: "l"(&g_count), "r"(0u) : "memory");
        }
    }
}

extern "C" void kernel_launch(void* const* d_in, const int* in_sizes, int n_in,
                              void* d_out, int out_size)
{
    const float4* y4 = (const float4*)d_in[0];   // yhat_xhat
    const float4* x4 = (const float4*)d_in[1];   // xhat
    const float2* z2 = (const float2*)d_in[2];   // z_xhat
    float* out = (float*)d_out;

    fused_loss_kernel<<<GRID, TPB>>>(y4, x4, z2, out);
}